// round 14
// baseline (speedup 1.0000x reference)
#include <cuda_runtime.h>
#include <math.h>

#define BATCH 2
#define SEQ   2048
#define DIM   1024
#define HEADS 16
#define HDIM  64
#define MROWS (BATCH * SEQ)     /* 4096 */
#define NQKV  (3 * DIM)         /* 3072 */
#define QKLD  (2 * DIM)         /* row stride of qk buffer */

// Scratch (device globals; total 84MB, matching the proven-good budget).
__device__ float g_qk [(size_t)MROWS * QKLD];                   // 33.6 MB (q|k per row)
__device__ float g_vt [(size_t)(BATCH * DIM) * SEQ];            // 16.8 MB (v transposed)
__device__ float g_att[(size_t)MROWS * DIM];                    // 16.8 MB (xr alias, then att)
__device__ float g_wrs[(size_t)DIM * NQKV + (size_t)DIM * DIM]; // 16.8 MB (wr_t | owr_t)

// ---------------------------------------------------------------------------
// helpers
// ---------------------------------------------------------------------------
__device__ __forceinline__ float tf32r(float x) {
    unsigned u;
    asm("cvt.rna.tf32.f32 %0, %1;" : "=r"(u) : "f"(x));
    return __uint_as_float(u);
}

__device__ __forceinline__ void mma_tf32(float c[4], const unsigned a[4], const unsigned b[2]) {
    asm volatile(
        "mma.sync.aligned.m16n8k8.row.col.f32.tf32.tf32.f32 "
        "{%0,%1,%2,%3}, {%4,%5,%6,%7}, {%8,%9}, {%0,%1,%2,%3};\n"
        : "+f"(c[0]), "+f"(c[1]), "+f"(c[2]), "+f"(c[3])
        : "r"(a[0]), "r"(a[1]), "r"(a[2]), "r"(a[3]), "r"(b[0]), "r"(b[1]));
}

// ldmatrix: tf32 fragments via b16 8x8 matrices (each = one 8x4 tf32 block).
__device__ __forceinline__ void ldsm_x4(unsigned r[4], const float* p) {
    unsigned a = (unsigned)__cvta_generic_to_shared(p);
    asm volatile("ldmatrix.sync.aligned.m8n8.x4.shared.b16 {%0,%1,%2,%3}, [%4];"
                 : "=r"(r[0]), "=r"(r[1]), "=r"(r[2]), "=r"(r[3]) : "r"(a));
}

__device__ __forceinline__ void cp16(float* s, const float* g) {
    unsigned sa = (unsigned)__cvta_generic_to_shared(s);
    asm volatile("cp.async.cg.shared.global [%0], [%1], 16;\n" :: "r"(sa), "l"(g));
}
#define CP_COMMIT() asm volatile("cp.async.commit_group;\n" ::: "memory")
#define CP_WAIT(N)  asm volatile("cp.async.wait_group %0;\n" :: "n"(N) : "memory")

// ---------------------------------------------------------------------------
// Prep kernels
// ---------------------------------------------------------------------------
__global__ __launch_bounds__(256) void round_tf32_kernel(
    const float* __restrict__ src, float* __restrict__ dst, int n4)
{
    const int i = (blockIdx.x * 256 + threadIdx.x);
    if (i < n4) {
        float4 v = ((const float4*)src)[i];
        ((float4*)dst)[i] = make_float4(tf32r(v.x), tf32r(v.y), tf32r(v.z), tf32r(v.w));
    }
}

// dst[n][k] = round(src[k][n]);  src is [K][N]. 32x32 smem tiles, 256 threads.
__global__ __launch_bounds__(256) void round_transpose_kernel(
    const float* __restrict__ src, float* __restrict__ dst, int K, int N)
{
    __shared__ float t[32][33];
    const int n0 = blockIdx.x * 32;
    const int k0 = blockIdx.y * 32;
    const int tx = threadIdx.x & 31;
    const int ty = threadIdx.x >> 5;       // 0..7
#pragma unroll
    for (int i = 0; i < 32; i += 8)
        t[ty + i][tx] = src[(size_t)(k0 + ty + i) * N + n0 + tx];
    __syncthreads();
#pragma unroll
    for (int i = 0; i < 32; i += 8)
        dst[(size_t)(n0 + ty + i) * K + k0 + tx] = tf32r(t[tx][ty + i]);
}

// ---------------------------------------------------------------------------
// TF32 GEMM: C[M,N] = A[M,K] @ Wt[N,K]^T + bias[N]   (A, Wt pre-rounded)
// Block 128x128x32, 8 warps (2x4), warp tile 64x32, mma m16n8k8, all LDSM.
// 2-stage cp.async ring, 2 CTAs/SM.
// VT mode: CTAs with n0 >= 2*DIM (the V third of the QKV projection) write
// their output TRANSPOSED into Cvt[b*1024 + (col-2048)][s] instead of C.
// ---------------------------------------------------------------------------
#define BM 128
#define BN 128
#define BK 32
#define TP 36                                  /* tile pitch (floats) */
#define TSZ (128 * TP)                         /* one tile (floats)   */
#define GEMM_SMEM ((4 * TSZ) * (int)sizeof(float))   /* 73728 B */

template <bool ROUND_OUT, bool VT>
__global__ __launch_bounds__(256, 2) void gemm_tf32_kernel(
    const float* __restrict__ A, const float* __restrict__ Wt,
    const float* __restrict__ bias, float* __restrict__ C,
    float* __restrict__ Cvt,
    int M, int N, int K, int ldc)
{
    extern __shared__ float dyn[];
    float* As = dyn;               // [2][128][TP]
    float* Bs = dyn + 2 * TSZ;     // [2][128][TP]  (rows = n)

    const int tid  = threadIdx.x;
    const int lane = tid & 31;
    const int warp = tid >> 5;
    const int wr   = warp >> 2;          // 0..1
    const int wc   = warp & 3;           // 0..3

    const int m0 = blockIdx.y * BM;
    const int n0 = blockIdx.x * BN;

    const int lrow = tid >> 3;           // 0..31 (rows lrow + 32*i)
    const int lcol = (tid & 7) * 4;      // k offset within BK

    const int T = K / BK;

    auto loadtile = [&](int t) {
        float* as = As + (t & 1) * TSZ;
        float* bs = Bs + (t & 1) * TSZ;
        const int k0 = t * BK;
#pragma unroll
        for (int i = 0; i < 4; ++i)
            cp16(&as[(lrow + 32 * i) * TP + lcol],
                 A + (size_t)(m0 + lrow + 32 * i) * K + k0 + lcol);
#pragma unroll
        for (int i = 0; i < 4; ++i)
            cp16(&bs[(lrow + 32 * i) * TP + lcol],
                 Wt + (size_t)(n0 + lrow + 32 * i) * K + k0 + lcol);
        CP_COMMIT();
    };

    float acc[4][4][4];
#pragma unroll
    for (int mi = 0; mi < 4; ++mi)
#pragma unroll
        for (int nj = 0; nj < 4; ++nj)
#pragma unroll
            for (int r = 0; r < 4; ++r) acc[mi][nj][r] = 0.f;

    // LDSM lane->row/k mapping (same for A and B tiles)
    const int sm_row = lane & 15;
    const int sm_k4  = (lane & 16) ? 4 : 0;
    const int b_row  = ((lane & 16) ? 8 : 0) + (lane & 7);
    const int b_k4   = (lane & 8) ? 4 : 0;

    loadtile(0);

    for (int t = 0; t < T; ++t) {
        CP_WAIT(0);
        __syncthreads();
        if (t + 1 < T) loadtile(t + 1);

        const float* as = As + (t & 1) * TSZ;
        const float* bs = Bs + (t & 1) * TSZ;

#pragma unroll
        for (int ks = 0; ks < 4; ++ks) {
            unsigned af[4][4], bq[2][4];
            const float* ab = as + (wr * 64 + sm_row) * TP + ks * 8 + sm_k4;
            const float* bb = bs + (wc * 32 + b_row) * TP + ks * 8 + b_k4;
#pragma unroll
            for (int mi = 0; mi < 4; ++mi)
                ldsm_x4(af[mi], ab + mi * 16 * TP);
#pragma unroll
            for (int p = 0; p < 2; ++p)
                ldsm_x4(bq[p], bb + p * 16 * TP);
#pragma unroll
            for (int mi = 0; mi < 4; ++mi)
#pragma unroll
                for (int p = 0; p < 2; ++p) {
                    mma_tf32(acc[mi][2 * p],     af[mi], &bq[p][0]);
                    mma_tf32(acc[mi][2 * p + 1], af[mi], &bq[p][2]);
                }
        }
    }

    // epilogue: bias + store
    const int grp = lane >> 2;
    const int qid = lane & 3;
    const bool vmode = VT && (n0 >= 2 * DIM);
#pragma unroll
    for (int mi = 0; mi < 4; ++mi) {
#pragma unroll
        for (int nj = 0; nj < 4; ++nj) {
            const int row = m0 + wr * 64 + mi * 16 + grp;
            const int col = n0 + wc * 32 + nj * 8 + 2 * qid;
            const float b0 = bias[col];
            const float b1 = bias[col + 1];
            float c00 = acc[mi][nj][0] + b0, c01 = acc[mi][nj][1] + b1;
            float c10 = acc[mi][nj][2] + b0, c11 = acc[mi][nj][3] + b1;
            if (ROUND_OUT) {
                c00 = tf32r(c00); c01 = tf32r(c01);
                c10 = tf32r(c10); c11 = tf32r(c11);
            }
            if (vmode) {
                // V third: write transposed  vt[(b*1024 + (col-2048))][s]
                const int bb = row >> 11;          // batch
                const int ss = row & (SEQ - 1);    // sequence pos
                const int cc = col - 2 * DIM;      // h*64 + d
                float* base = Cvt + ((size_t)(bb * DIM + cc)) * SEQ + ss;
                base[0]       = c00;
                base[SEQ]     = c01;   // col+1
                base[8]       = c10;   // row+8
                base[SEQ + 8] = c11;
            } else {
                *(float2*)&C[(size_t)row * ldc + col] = make_float2(c00, c01);
                *(float2*)&C[(size_t)(row + 8) * ldc + col] = make_float2(c10, c11);
            }
        }
    }
}

// ---------------------------------------------------------------------------
// Flash attention (causal), tf32, all MMA operands via LDSM.
// Q/K from qk buffer [row][2048]; V from vt [b*1024+h*64+d][s] (B-layout!).
// 68KB smem, 3 CTAs/SM. Grid: (S/64, B*H), 128 threads (4 warps).
// ---------------------------------------------------------------------------
#define QP 68   /* pitch for Qs/Ks/Ps/Vt tiles */
#define FLASH_SMEM ((4 * 64 * QP) * (int)sizeof(float))  /* 69632 B */

__global__ __launch_bounds__(128) void flash_tf32_kernel(
    const float* __restrict__ qk, const float* __restrict__ vt,
    float* __restrict__ out)
{
    extern __shared__ float smf[];
    float* Qs  = smf;               // 64*QP
    float* Ks  = Qs + 64 * QP;      // 64*QP
    float* Ps  = Ks + 64 * QP;      // 64*QP
    float* Vts = Ps + 64 * QP;      // 64*QP  (rows = d, cols = kv)

    const int tid  = threadIdx.x;
    const int lane = tid & 31;
    const int warp = tid >> 5;     // 0..3, 16 queries each
    const int grp  = lane >> 2;
    const int qid  = lane & 3;

    const int bh = blockIdx.y;
    const int b  = bh / HEADS;
    const int h  = bh % HEADS;
    const int qt = gridDim.x - 1 - blockIdx.x;   // heavy tiles first
    const int q0 = qt * 64;
    const float scale = 0.125f;

    const float* qbase = qk + (size_t)(b * SEQ) * QKLD + h * HDIM;
    const float* kbase = qbase + DIM;
    const float* vbase = vt + ((size_t)(b * DIM + h * HDIM)) * SEQ;

    const int lr = tid >> 4;            // 0..7
    const int lc = (tid & 15) * 4;      // 0..60

    // Load Q tile (pre-rounded)
#pragma unroll
    for (int i = 0; i < 8; ++i) {
        float4 v = *(const float4*)(qbase + (size_t)(q0 + lr + 8 * i) * QKLD + lc);
        *(float4*)&Qs[(lr + 8 * i) * QP + lc] = v;
    }
    __syncthreads();

    // Q fragments register-resident (LDSM A-frags)
    const int a_row = lane & 15;
    const int a_k4  = (lane & 16) ? 4 : 0;
    unsigned qf[8][4];
#pragma unroll
    for (int ks = 0; ks < 8; ++ks)
        ldsm_x4(qf[ks], &Qs[(warp * 16 + a_row) * QP + ks * 8 + a_k4]);

    float m0r = -INFINITY, m1r = -INFINITY, l0 = 0.f, l1 = 0.f;
    float o[8][4];
#pragma unroll
    for (int j = 0; j < 8; ++j)
#pragma unroll
        for (int r = 0; r < 4; ++r) o[j][r] = 0.f;

    // B-frag LDSM mapping (K and Vt tiles)
    const int b_row = ((lane & 16) ? 8 : 0) + (lane & 7);
    const int b_k4  = (lane & 8) ? 4 : 0;

    const int ntiles = qt + 1;
    for (int t = 0; t < ntiles; ++t) {
        const int k0 = t * 64;
        __syncthreads();
#pragma unroll
        for (int i = 0; i < 8; ++i) {
            const int row = lr + 8 * i;
            // K tile: [kv][d]
            float4 kv = *(const float4*)(kbase + (size_t)(k0 + row) * QKLD + lc);
            *(float4*)&Ks[row * QP + lc] = kv;
            // V tile transposed: [d][kv]  (row = d, kv contiguous)
            float4 vv = *(const float4*)(vbase + (size_t)row * SEQ + k0 + lc);
            *(float4*)&Vts[row * QP + lc] = vv;
        }
        __syncthreads();

        // S = Q K^T  (warp tile 16x64)
        float s[8][4];
#pragma unroll
        for (int j = 0; j < 8; ++j)
            s[j][0] = s[j][1] = s[j][2] = s[j][3] = 0.f;
#pragma unroll
        for (int ks = 0; ks < 8; ++ks) {
#pragma unroll
            for (int jj = 0; jj < 4; ++jj) {
                unsigned kq[4];
                ldsm_x4(kq, &Ks[(jj * 16 + b_row) * QP + ks * 8 + b_k4]);
                mma_tf32(s[2 * jj],     qf[ks], &kq[0]);
                mma_tf32(s[2 * jj + 1], qf[ks], &kq[2]);
            }
        }

        // scale + causal mask (diag tile only)
        const bool diag = (t == ntiles - 1);
        const int qi0 = q0 + warp * 16 + grp;
#pragma unroll
        for (int j = 0; j < 8; ++j) {
#pragma unroll
            for (int r = 0; r < 4; ++r) {
                float v = s[j][r] * scale;
                if (diag) {
                    const int kj = k0 + j * 8 + 2 * qid + (r & 1);
                    const int qi = qi0 + ((r >= 2) ? 8 : 0);
                    if (kj > qi) v = -INFINITY;
                }
                s[j][r] = v;
            }
        }

        // online softmax (rows grp and grp+8)
        float mx0 = -INFINITY, mx1 = -INFINITY;
#pragma unroll
        for (int j = 0; j < 8; ++j) {
            mx0 = fmaxf(mx0, fmaxf(s[j][0], s[j][1]));
            mx1 = fmaxf(mx1, fmaxf(s[j][2], s[j][3]));
        }
        mx0 = fmaxf(mx0, __shfl_xor_sync(0xffffffffu, mx0, 1));
        mx0 = fmaxf(mx0, __shfl_xor_sync(0xffffffffu, mx0, 2));
        mx1 = fmaxf(mx1, __shfl_xor_sync(0xffffffffu, mx1, 1));
        mx1 = fmaxf(mx1, __shfl_xor_sync(0xffffffffu, mx1, 2));

        const float nm0 = fmaxf(m0r, mx0);
        const float nm1 = fmaxf(m1r, mx1);
        const float corr0 = __expf(m0r - nm0);
        const float corr1 = __expf(m1r - nm1);
        m0r = nm0; m1r = nm1;

        float sum0 = 0.f, sum1 = 0.f;
#pragma unroll
        for (int j = 0; j < 8; ++j) {
            s[j][0] = __expf(s[j][0] - nm0);
            s[j][1] = __expf(s[j][1] - nm0);
            s[j][2] = __expf(s[j][2] - nm1);
            s[j][3] = __expf(s[j][3] - nm1);
            sum0 += s[j][0] + s[j][1];
            sum1 += s[j][2] + s[j][3];
        }
        sum0 += __shfl_xor_sync(0xffffffffu, sum0, 1);
        sum0 += __shfl_xor_sync(0xffffffffu, sum0, 2);
        sum1 += __shfl_xor_sync(0xffffffffu, sum1, 1);
        sum1 += __shfl_xor_sync(0xffffffffu, sum1, 2);
        l0 = l0 * corr0 + sum0;
        l1 = l1 * corr1 + sum1;
#pragma unroll
        for (int j = 0; j < 8; ++j) {
            o[j][0] *= corr0; o[j][1] *= corr0;
            o[j][2] *= corr1; o[j][3] *= corr1;
        }

        // P fragments -> smem (C-layout -> A-layout), warp-private
#pragma unroll
        for (int j = 0; j < 8; ++j) {
            float* p0 = &Ps[(warp * 16 + grp) * QP + j * 8 + 2 * qid];
            float* p1 = &Ps[(warp * 16 + grp + 8) * QP + j * 8 + 2 * qid];
            *(float2*)p0 = make_float2(tf32r(s[j][0]), tf32r(s[j][1]));
            *(float2*)p1 = make_float2(tf32r(s[j][2]), tf32r(s[j][3]));
        }
        __syncwarp();

        // O += P @ V  (P and V both via LDSM; V rows = d, k = kv)
#pragma unroll
        for (int ks = 0; ks < 8; ++ks) {
            unsigned pf[4];
            ldsm_x4(pf, &Ps[(warp * 16 + a_row) * QP + ks * 8 + a_k4]);
#pragma unroll
            for (int dd = 0; dd < 4; ++dd) {
                unsigned vq[4];
                ldsm_x4(vq, &Vts[(dd * 16 + b_row) * QP + ks * 8 + b_k4]);
                mma_tf32(o[2 * dd],     pf, &vq[0]);
                mma_tf32(o[2 * dd + 1], pf, &vq[2]);
            }
        }
    }

    // write normalized output (tf32-rounded: feeds out-proj MMA directly)
    const float inv0 = 1.0f / l0;
    const float inv1 = 1.0f / l1;
    const int row0 = q0 + warp * 16 + grp;
#pragma unroll
    for (int j = 0; j < 8; ++j) {
        const int col = h * HDIM + j * 8 + 2 * qid;
        *(float2*)&out[((size_t)(b * SEQ) + row0) * DIM + col] =
            make_float2(tf32r(o[j][0] * inv0), tf32r(o[j][1] * inv0));
        *(float2*)&out[((size_t)(b * SEQ) + row0 + 8) * DIM + col] =
            make_float2(tf32r(o[j][2] * inv1), tf32r(o[j][3] * inv1));
    }
}

// ---------------------------------------------------------------------------
extern "C" void kernel_launch(void* const* d_in, const int* in_sizes, int n_in,
                              void* d_out, int out_size)
{
    const float* x      = (const float*)d_in[0];   // [B,S,D]
    const float* qkv_w  = (const float*)d_in[1];   // [D, 3D]
    const float* qkv_b  = (const float*)d_in[2];   // [3D]
    const float* out_w  = (const float*)d_in[3];   // [D, D]
    const float* out_b  = (const float*)d_in[4];   // [D]
    float* out = (float*)d_out;

    float *qk_buf, *vt_buf, *att_buf, *wrs;
    cudaGetSymbolAddress((void**)&qk_buf, g_qk);
    cudaGetSymbolAddress((void**)&vt_buf, g_vt);
    cudaGetSymbolAddress((void**)&att_buf, g_att);
    cudaGetSymbolAddress((void**)&wrs, g_wrs);

    // xr aliases att_buf (dead before flash writes att); weights transposed+rounded.
    float* xr    = att_buf;
    float* wr_t  = wrs;                                  // [NQKV][DIM]
    float* owr_t = wrs + (size_t)DIM * NQKV;             // [DIM][DIM]

    cudaFuncSetAttribute(gemm_tf32_kernel<true, true>,
                         cudaFuncAttributeMaxDynamicSharedMemorySize, GEMM_SMEM);
    cudaFuncSetAttribute(gemm_tf32_kernel<false, false>,
                         cudaFuncAttributeMaxDynamicSharedMemorySize, GEMM_SMEM);
    cudaFuncSetAttribute(flash_tf32_kernel,
                         cudaFuncAttributeMaxDynamicSharedMemorySize, FLASH_SMEM);

    // 0) prep: round x; round+transpose both weight matrices
    {
        int n4 = MROWS * DIM / 4;
        round_tf32_kernel<<<(n4 + 255) / 256, 256>>>(x, xr, n4);
        dim3 g1(NQKV / 32, DIM / 32);
        round_transpose_kernel<<<g1, 256>>>(qkv_w, wr_t, DIM, NQKV);
        dim3 g2(DIM / 32, DIM / 32);
        round_transpose_kernel<<<g2, 256>>>(out_w, owr_t, DIM, DIM);
    }
    // 1) QKV projection: Q,K -> qk_buf [row][2048]; V -> vt_buf transposed
    {
        dim3 grid(NQKV / BN, MROWS / BM);
        gemm_tf32_kernel<true, true><<<grid, 256, GEMM_SMEM>>>(
            xr, wr_t, qkv_b, qk_buf, vt_buf, MROWS, NQKV, DIM, QKLD);
    }
    // 2) Causal flash attention (overwrites xr with att)
    {
        dim3 grid(SEQ / 64, BATCH * HEADS);
        flash_tf32_kernel<<<grid, 128, FLASH_SMEM>>>(qk_buf, vt_buf, att_buf);
    }
    // 3) Output projection (exact fp32 out)
    {
        dim3 grid(DIM / BN, MROWS / BM);
        gemm_tf32_kernel<false, false><<<grid, 256, GEMM_SMEM>>>(
            att_buf, owr_t, out_b, out, nullptr, MROWS, DIM, DIM, DIM);
    }
}

// round 16
// speedup vs baseline: 1.6570x; 1.6570x over previous
#include <cuda_runtime.h>
#include <cuda_fp16.h>
#include <math.h>

#define BATCH 2
#define SEQ   2048
#define DIM   1024
#define HEADS 16
#define HDIM  64
#define MROWS (BATCH * SEQ)     /* 4096 */
#define NQKV  (3 * DIM)         /* 3072 */
#define QKLD  (2 * DIM)         /* row stride (halves) of qk buffer */

// Scratch (device globals; fp16 → ~42MB total, well under proven budget).
__device__ __half g_qk [(size_t)MROWS * QKLD];                   // 16.8 MB (q|k per row)
__device__ __half g_vt [(size_t)(BATCH * DIM) * SEQ];            //  8.4 MB (v transposed [b*1024+h*64+d][s])
__device__ __half g_att[(size_t)MROWS * DIM];                    //  8.4 MB (xr alias, then att)
__device__ __half g_wrs[(size_t)DIM * NQKV + (size_t)DIM * DIM]; //  8.4 MB (wr_t | owr_t)

// ---------------------------------------------------------------------------
// helpers
// ---------------------------------------------------------------------------
__device__ __forceinline__ void mma_f16(float c[4], const unsigned a[4], const unsigned b[2]) {
    asm volatile(
        "mma.sync.aligned.m16n8k16.row.col.f32.f16.f16.f32 "
        "{%0,%1,%2,%3}, {%4,%5,%6,%7}, {%8,%9}, {%0,%1,%2,%3};\n"
        : "+f"(c[0]), "+f"(c[1]), "+f"(c[2]), "+f"(c[3])
        : "r"(a[0]), "r"(a[1]), "r"(a[2]), "r"(a[3]), "r"(b[0]), "r"(b[1]));
}

__device__ __forceinline__ void ldsm_x4(unsigned r[4], const __half* p) {
    unsigned a = (unsigned)__cvta_generic_to_shared(p);
    asm volatile("ldmatrix.sync.aligned.m8n8.x4.shared.b16 {%0,%1,%2,%3}, [%4];"
                 : "=r"(r[0]), "=r"(r[1]), "=r"(r[2]), "=r"(r[3]) : "r"(a));
}

__device__ __forceinline__ void cp16(__half* s, const __half* g) {
    unsigned sa = (unsigned)__cvta_generic_to_shared(s);
    asm volatile("cp.async.cg.shared.global [%0], [%1], 16;\n" :: "r"(sa), "l"(g));
}
#define CP_COMMIT() asm volatile("cp.async.commit_group;\n" ::: "memory")
#define CP_WAIT(N)  asm volatile("cp.async.wait_group %0;\n" :: "n"(N) : "memory")

// ---------------------------------------------------------------------------
// Prep kernels
// ---------------------------------------------------------------------------
__global__ __launch_bounds__(256) void round_half_kernel(
    const float* __restrict__ src, __half* __restrict__ dst, int n4)
{
    const int i = (blockIdx.x * 256 + threadIdx.x);
    if (i < n4) {
        float4 v = ((const float4*)src)[i];
        ((__half2*)dst)[2 * i]     = __floats2half2_rn(v.x, v.y);
        ((__half2*)dst)[2 * i + 1] = __floats2half2_rn(v.z, v.w);
    }
}

// dst[n][k] = half(src[k][n]);  src fp32 [K][N]. 32x32 smem tiles.
__global__ __launch_bounds__(256) void round_transpose_kernel(
    const float* __restrict__ src, __half* __restrict__ dst, int K, int N)
{
    __shared__ float t[32][33];
    const int n0 = blockIdx.x * 32;
    const int k0 = blockIdx.y * 32;
    const int tx = threadIdx.x & 31;
    const int ty = threadIdx.x >> 5;       // 0..7
#pragma unroll
    for (int i = 0; i < 32; i += 8)
        t[ty + i][tx] = src[(size_t)(k0 + ty + i) * N + n0 + tx];
    __syncthreads();
#pragma unroll
    for (int i = 0; i < 32; i += 8)
        dst[(size_t)(n0 + ty + i) * K + k0 + tx] = __float2half_rn(t[tx][ty + i]);
}

// ---------------------------------------------------------------------------
// FP16 GEMM: C[M,N] = A[M,K] @ Wt[N,K]^T + bias[N]   (A, Wt fp16)
// Block 128x128x64, 8 warps (2x4), warp tile 64x32, mma m16n8k16, all LDSM.
// 2-stage cp.async ring, 2 CTAs/SM, 16 K-iters.
// VT mode: CTAs with n0 >= 2*DIM write transposed into Cvt (fp16).
// ---------------------------------------------------------------------------
#define BM 128
#define BN 128
#define BK 64
#define TPH 72                                 /* tile pitch (halves): 144B rows */
#define TSZH (128 * TPH)                       /* one tile (halves) */
#define GEMM_SMEM ((4 * TSZH) * (int)sizeof(__half))   /* 73728 B */

template <bool HALF_OUT, bool VT>
__global__ __launch_bounds__(256, 2) void gemm_f16_kernel(
    const __half* __restrict__ A, const __half* __restrict__ Wt,
    const float* __restrict__ bias,
    __half* __restrict__ Ch, float* __restrict__ Cf, __half* __restrict__ Cvt,
    int M, int N, int K, int ldc)
{
    extern __shared__ __half hdyn[];
    __half* As = hdyn;                // [2][128][TPH]
    __half* Bs = hdyn + 2 * TSZH;     // [2][128][TPH]  (rows = n)

    const int tid  = threadIdx.x;
    const int lane = tid & 31;
    const int warp = tid >> 5;
    const int wr   = warp >> 2;          // 0..1
    const int wc   = warp & 3;           // 0..3

    const int m0 = blockIdx.y * BM;
    const int n0 = blockIdx.x * BN;

    const int lrow = tid >> 3;           // 0..31 (rows lrow + 32*i)
    const int lcol = (tid & 7) * 8;      // half offset within BK (0..56)

    const int T = K / BK;

    auto loadtile = [&](int t) {
        __half* as = As + (t & 1) * TSZH;
        __half* bs = Bs + (t & 1) * TSZH;
        const int k0 = t * BK;
#pragma unroll
        for (int i = 0; i < 4; ++i)
            cp16(&as[(lrow + 32 * i) * TPH + lcol],
                 A + (size_t)(m0 + lrow + 32 * i) * K + k0 + lcol);
#pragma unroll
        for (int i = 0; i < 4; ++i)
            cp16(&bs[(lrow + 32 * i) * TPH + lcol],
                 Wt + (size_t)(n0 + lrow + 32 * i) * K + k0 + lcol);
        CP_COMMIT();
    };

    float acc[4][4][4];
#pragma unroll
    for (int mi = 0; mi < 4; ++mi)
#pragma unroll
        for (int nj = 0; nj < 4; ++nj)
#pragma unroll
            for (int r = 0; r < 4; ++r) acc[mi][nj][r] = 0.f;

    // LDSM lane mapping (A and B identical): row = lane&15, k-half = (lane>>4)*8
    const int sm_row = lane & 15;
    const int sm_k8  = (lane >> 4) * 8;

    loadtile(0);

    for (int t = 0; t < T; ++t) {
        CP_WAIT(0);
        __syncthreads();
        if (t + 1 < T) loadtile(t + 1);

        const __half* as = As + (t & 1) * TSZH;
        const __half* bs = Bs + (t & 1) * TSZH;

#pragma unroll
        for (int ks = 0; ks < 4; ++ks) {        // 4 k-steps of 16
            unsigned af[4][4], bq[2][4];
            const __half* ab = as + (wr * 64 + sm_row) * TPH + ks * 16 + sm_k8;
            const __half* bb = bs + (wc * 32 + sm_row) * TPH + ks * 16 + sm_k8;
#pragma unroll
            for (int mi = 0; mi < 4; ++mi)
                ldsm_x4(af[mi], ab + mi * 16 * TPH);
#pragma unroll
            for (int p = 0; p < 2; ++p)
                ldsm_x4(bq[p], bb + p * 16 * TPH);
#pragma unroll
            for (int mi = 0; mi < 4; ++mi)
#pragma unroll
                for (int p = 0; p < 2; ++p) {
                    unsigned b0[2] = {bq[p][0], bq[p][2]};
                    unsigned b1[2] = {bq[p][1], bq[p][3]};
                    mma_f16(acc[mi][2 * p],     af[mi], b0);
                    mma_f16(acc[mi][2 * p + 1], af[mi], b1);
                }
        }
    }

    // epilogue: bias + store
    const int grp = lane >> 2;
    const int qid = lane & 3;
    const bool vmode = VT && (n0 >= 2 * DIM);
#pragma unroll
    for (int mi = 0; mi < 4; ++mi) {
#pragma unroll
        for (int nj = 0; nj < 4; ++nj) {
            const int row = m0 + wr * 64 + mi * 16 + grp;
            const int col = n0 + wc * 32 + nj * 8 + 2 * qid;
            const float b0 = bias[col];
            const float b1 = bias[col + 1];
            const float c00 = acc[mi][nj][0] + b0, c01 = acc[mi][nj][1] + b1;
            const float c10 = acc[mi][nj][2] + b0, c11 = acc[mi][nj][3] + b1;
            if (HALF_OUT) {
                if (vmode) {
                    // V third: vt[(b*1024 + (col-2048))][s], fp16 scalar scatter
                    const int bb = row >> 11;
                    const int ss = row & (SEQ - 1);
                    const int cc = col - 2 * DIM;
                    __half* base = Cvt + ((size_t)(bb * DIM + cc)) * SEQ + ss;
                    base[0]       = __float2half_rn(c00);
                    base[SEQ]     = __float2half_rn(c01);
                    base[8]       = __float2half_rn(c10);
                    base[SEQ + 8] = __float2half_rn(c11);
                } else {
                    *(__half2*)&Ch[(size_t)row * ldc + col] = __floats2half2_rn(c00, c01);
                    *(__half2*)&Ch[(size_t)(row + 8) * ldc + col] = __floats2half2_rn(c10, c11);
                }
            } else {
                *(float2*)&Cf[(size_t)row * ldc + col] = make_float2(c00, c01);
                *(float2*)&Cf[(size_t)(row + 8) * ldc + col] = make_float2(c10, c11);
            }
        }
    }
}

// ---------------------------------------------------------------------------
// Flash attention (causal), fp16 MMA (m16n8k16), all operands via LDSM.
// Q/K from qk [row][2048] fp16; V from vt [b*1024+h*64+d][s] fp16 (B-layout).
// 36.9KB smem -> 4 CTAs/SM. Grid: (S/64, B*H), 128 threads (4 warps).
// ---------------------------------------------------------------------------
#define FLASH_SMEM ((4 * 64 * TPH) * (int)sizeof(__half))  /* 36864 B */

__global__ __launch_bounds__(128) void flash_f16_kernel(
    const __half* __restrict__ qk, const __half* __restrict__ vt,
    __half* __restrict__ att)
{
    extern __shared__ __half hsm[];
    __half* Qs  = hsm;                // 64*TPH
    __half* Ks  = Qs + 64 * TPH;      // 64*TPH  (rows = kv)
    __half* Ps  = Ks + 64 * TPH;      // 64*TPH
    __half* Vts = Ps + 64 * TPH;      // 64*TPH  (rows = d, cols = kv)

    const int tid  = threadIdx.x;
    const int lane = tid & 31;
    const int warp = tid >> 5;     // 0..3, 16 queries each
    const int grp  = lane >> 2;
    const int qid  = lane & 3;

    const int bh = blockIdx.y;
    const int b  = bh / HEADS;
    const int h  = bh % HEADS;
    const int qt = gridDim.x - 1 - blockIdx.x;   // heavy tiles first
    const int q0 = qt * 64;
    const float scale = 0.125f;

    const __half* qbase = qk + (size_t)(b * SEQ) * QKLD + h * HDIM;
    const __half* kbase = qbase + DIM;
    const __half* vbase = vt + ((size_t)(b * DIM + h * HDIM)) * SEQ;

    const int lr = tid >> 3;            // 0..15 (rows lr + 16*i)
    const int lc = (tid & 7) * 8;       // half offset 0..56

    // Load Q tile
#pragma unroll
    for (int i = 0; i < 4; ++i) {
        const int row = lr + 16 * i;
        *(uint4*)&Qs[row * TPH + lc] =
            *(const uint4*)(qbase + (size_t)(q0 + row) * QKLD + lc);
    }
    __syncthreads();

    // Q fragments register-resident (4 k-steps of 16 over HDIM=64)
    const int sm_row = lane & 15;
    const int sm_k8  = (lane >> 4) * 8;
    unsigned qf[4][4];
#pragma unroll
    for (int ks = 0; ks < 4; ++ks)
        ldsm_x4(qf[ks], &Qs[(warp * 16 + sm_row) * TPH + ks * 16 + sm_k8]);

    float m0r = -INFINITY, m1r = -INFINITY, l0 = 0.f, l1 = 0.f;
    float o[8][4];
#pragma unroll
    for (int j = 0; j < 8; ++j)
#pragma unroll
        for (int r = 0; r < 4; ++r) o[j][r] = 0.f;

    const int ntiles = qt + 1;
    for (int t = 0; t < ntiles; ++t) {
        const int k0 = t * 64;
        __syncthreads();
#pragma unroll
        for (int i = 0; i < 4; ++i) {
            const int row = lr + 16 * i;
            // K tile: [kv][d]
            *(uint4*)&Ks[row * TPH + lc] =
                *(const uint4*)(kbase + (size_t)(k0 + row) * QKLD + lc);
            // V tile: [d][kv]
            *(uint4*)&Vts[row * TPH + lc] =
                *(const uint4*)(vbase + (size_t)row * SEQ + k0 + lc);
        }
        __syncthreads();

        // S = Q K^T  (warp tile 16x64)
        float s[8][4];
#pragma unroll
        for (int j = 0; j < 8; ++j)
            s[j][0] = s[j][1] = s[j][2] = s[j][3] = 0.f;
#pragma unroll
        for (int ks = 0; ks < 4; ++ks) {
#pragma unroll
            for (int jj = 0; jj < 4; ++jj) {
                unsigned kq[4];
                ldsm_x4(kq, &Ks[(jj * 16 + sm_row) * TPH + ks * 16 + sm_k8]);
                unsigned b0[2] = {kq[0], kq[2]};
                unsigned b1[2] = {kq[1], kq[3]};
                mma_f16(s[2 * jj],     qf[ks], b0);
                mma_f16(s[2 * jj + 1], qf[ks], b1);
            }
        }

        // scale + causal mask (diag tile only)
        const bool diag = (t == ntiles - 1);
        const int qi0 = q0 + warp * 16 + grp;
#pragma unroll
        for (int j = 0; j < 8; ++j) {
#pragma unroll
            for (int r = 0; r < 4; ++r) {
                float v = s[j][r] * scale;
                if (diag) {
                    const int kj = k0 + j * 8 + 2 * qid + (r & 1);
                    const int qi = qi0 + ((r >= 2) ? 8 : 0);
                    if (kj > qi) v = -INFINITY;
                }
                s[j][r] = v;
            }
        }

        // online softmax (rows grp and grp+8)
        float mx0 = -INFINITY, mx1 = -INFINITY;
#pragma unroll
        for (int j = 0; j < 8; ++j) {
            mx0 = fmaxf(mx0, fmaxf(s[j][0], s[j][1]));
            mx1 = fmaxf(mx1, fmaxf(s[j][2], s[j][3]));
        }
        mx0 = fmaxf(mx0, __shfl_xor_sync(0xffffffffu, mx0, 1));
        mx0 = fmaxf(mx0, __shfl_xor_sync(0xffffffffu, mx0, 2));
        mx1 = fmaxf(mx1, __shfl_xor_sync(0xffffffffu, mx1, 1));
        mx1 = fmaxf(mx1, __shfl_xor_sync(0xffffffffu, mx1, 2));

        const float nm0 = fmaxf(m0r, mx0);
        const float nm1 = fmaxf(m1r, mx1);
        const float corr0 = __expf(m0r - nm0);
        const float corr1 = __expf(m1r - nm1);
        m0r = nm0; m1r = nm1;

        float sum0 = 0.f, sum1 = 0.f;
#pragma unroll
        for (int j = 0; j < 8; ++j) {
            s[j][0] = __expf(s[j][0] - nm0);
            s[j][1] = __expf(s[j][1] - nm0);
            s[j][2] = __expf(s[j][2] - nm1);
            s[j][3] = __expf(s[j][3] - nm1);
            sum0 += s[j][0] + s[j][1];
            sum1 += s[j][2] + s[j][3];
        }
        sum0 += __shfl_xor_sync(0xffffffffu, sum0, 1);
        sum0 += __shfl_xor_sync(0xffffffffu, sum0, 2);
        sum1 += __shfl_xor_sync(0xffffffffu, sum1, 1);
        sum1 += __shfl_xor_sync(0xffffffffu, sum1, 2);
        l0 = l0 * corr0 + sum0;
        l1 = l1 * corr1 + sum1;
#pragma unroll
        for (int j = 0; j < 8; ++j) {
            o[j][0] *= corr0; o[j][1] *= corr0;
            o[j][2] *= corr1; o[j][3] *= corr1;
        }

        // P fragments -> smem fp16 (C-layout -> A-layout), warp-private
#pragma unroll
        for (int j = 0; j < 8; ++j) {
            *(__half2*)&Ps[(warp * 16 + grp) * TPH + j * 8 + 2 * qid] =
                __floats2half2_rn(s[j][0], s[j][1]);
            *(__half2*)&Ps[(warp * 16 + grp + 8) * TPH + j * 8 + 2 * qid] =
                __floats2half2_rn(s[j][2], s[j][3]);
        }
        __syncwarp();

        // O += P @ V  (P A-frags, V B-frags, all LDSM; 4 kv k-steps of 16)
#pragma unroll
        for (int ks = 0; ks < 4; ++ks) {
            unsigned pf[4];
            ldsm_x4(pf, &Ps[(warp * 16 + sm_row) * TPH + ks * 16 + sm_k8]);
#pragma unroll
            for (int dd = 0; dd < 4; ++dd) {
                unsigned vq[4];
                ldsm_x4(vq, &Vts[(dd * 16 + sm_row) * TPH + ks * 16 + sm_k8]);
                unsigned b0[2] = {vq[0], vq[2]};
                unsigned b1[2] = {vq[1], vq[3]};
                mma_f16(o[2 * dd],     pf, b0);
                mma_f16(o[2 * dd + 1], pf, b1);
            }
        }
    }

    // write normalized output (fp16: feeds out-proj MMA directly)
    const float inv0 = 1.0f / l0;
    const float inv1 = 1.0f / l1;
    const int row0 = q0 + warp * 16 + grp;
#pragma unroll
    for (int j = 0; j < 8; ++j) {
        const int col = h * HDIM + j * 8 + 2 * qid;
        *(__half2*)&att[((size_t)(b * SEQ) + row0) * DIM + col] =
            __floats2half2_rn(o[j][0] * inv0, o[j][1] * inv0);
        *(__half2*)&att[((size_t)(b * SEQ) + row0 + 8) * DIM + col] =
            __floats2half2_rn(o[j][2] * inv1, o[j][3] * inv1);
    }
}

// ---------------------------------------------------------------------------
extern "C" void kernel_launch(void* const* d_in, const int* in_sizes, int n_in,
                              void* d_out, int out_size)
{
    const float* x      = (const float*)d_in[0];   // [B,S,D]
    const float* qkv_w  = (const float*)d_in[1];   // [D, 3D]
    const float* qkv_b  = (const float*)d_in[2];   // [3D]
    const float* out_w  = (const float*)d_in[3];   // [D, D]
    const float* out_b  = (const float*)d_in[4];   // [D]
    float* out = (float*)d_out;

    __half *qk_buf, *vt_buf, *att_buf, *wrs;
    cudaGetSymbolAddress((void**)&qk_buf, g_qk);
    cudaGetSymbolAddress((void**)&vt_buf, g_vt);
    cudaGetSymbolAddress((void**)&att_buf, g_att);
    cudaGetSymbolAddress((void**)&wrs, g_wrs);

    // xr aliases att_buf (dead before flash writes att); weights transposed fp16.
    __half* xr    = att_buf;
    __half* wr_t  = wrs;                                  // [NQKV][DIM]
    __half* owr_t = wrs + (size_t)DIM * NQKV;             // [DIM][DIM]

    cudaFuncSetAttribute(gemm_f16_kernel<true, true>,
                         cudaFuncAttributeMaxDynamicSharedMemorySize, GEMM_SMEM);
    cudaFuncSetAttribute(gemm_f16_kernel<false, false>,
                         cudaFuncAttributeMaxDynamicSharedMemorySize, GEMM_SMEM);
    cudaFuncSetAttribute(flash_f16_kernel,
                         cudaFuncAttributeMaxDynamicSharedMemorySize, FLASH_SMEM);

    // 0) prep: round x to fp16; round+transpose both weight matrices to fp16
    {
        int n4 = MROWS * DIM / 4;
        round_half_kernel<<<(n4 + 255) / 256, 256>>>(x, xr, n4);
        dim3 g1(NQKV / 32, DIM / 32);
        round_transpose_kernel<<<g1, 256>>>(qkv_w, wr_t, DIM, NQKV);
        dim3 g2(DIM / 32, DIM / 32);
        round_transpose_kernel<<<g2, 256>>>(out_w, owr_t, DIM, DIM);
    }
    // 1) QKV projection: Q,K -> qk_buf [row][2048] fp16; V -> vt_buf transposed fp16
    {
        dim3 grid(NQKV / BN, MROWS / BM);
        gemm_f16_kernel<true, true><<<grid, 256, GEMM_SMEM>>>(
            xr, wr_t, qkv_b, qk_buf, nullptr, vt_buf, MROWS, NQKV, DIM, QKLD);
    }
    // 2) Causal flash attention (overwrites xr with att)
    {
        dim3 grid(SEQ / 64, BATCH * HEADS);
        flash_f16_kernel<<<grid, 128, FLASH_SMEM>>>(qk_buf, vt_buf, att_buf);
    }
    // 3) Output projection (fp32 out)
    {
        dim3 grid(DIM / BN, MROWS / BM);
        gemm_f16_kernel<false, false><<<grid, 256, GEMM_SMEM>>>(
            att_buf, owr_t, out_b, nullptr, out, nullptr, MROWS, DIM, DIM, DIM);
    }
}